// round 1
// baseline (speedup 1.0000x reference)
#include <cuda_runtime.h>
#include <math.h>

// ---------------- static problem constants ----------------
#define BATCH   64
#define NTOT    3137          // 56*56+1
#define CIN     96
#define COUT    192
#define NHEAD   2
#define HDIM    96
#define HFS     56
#define QH      28
#define KH      14
#define NQ      785           // 28*28+1
#define NK      197           // 14*14+1
#define SCALE   0.10206207261596577f   // 96^-0.5

// ---------------- scratch (device globals; no allocs allowed) ----------------
__device__ float g_qln[BATCH * NQ * CIN];
__device__ float g_kln[BATCH * NK * CIN];
__device__ float g_vln[BATCH * NK * CIN];
__device__ float g_qp [BATCH * NQ * COUT];
__device__ float g_kp [BATCH * NK * COUT];
__device__ float g_vp [BATCH * NK * COUT];

// =====================================================================
// Kernel 1: depthwise 3x3 pool (stride s, pad 1) + LayerNorm over C=96
// one warp per output token; lane owns channels {lane, lane+32, lane+64}
// =====================================================================
__global__ void pool_ln_kernel(const float* __restrict__ hs,
                               const float* __restrict__ pw,     // (96,1,3,3)
                               const float* __restrict__ gam,
                               const float* __restrict__ bet,
                               float* __restrict__ out,
                               int stride, int Wout, int ntok)
{
    int warp = threadIdx.x >> 5;
    int lane = threadIdx.x & 31;
    int tok  = blockIdx.x * (blockDim.x >> 5) + warp;
    if (tok >= BATCH * ntok) return;
    int b = tok / ntok;
    int t = tok - b * ntok;

    float v0 = 0.f, v1 = 0.f, v2 = 0.f;
    if (t == 0) {
        const float* p = hs + (size_t)b * NTOT * CIN;
        v0 = p[lane]; v1 = p[lane + 32]; v2 = p[lane + 64];
    } else {
        int s   = t - 1;
        int y   = s / Wout, x = s - y * Wout;
        int iy0 = y * stride - 1, ix0 = x * stride - 1;
        #pragma unroll
        for (int dy = 0; dy < 3; dy++) {
            int iy = iy0 + dy;
            if (iy < 0 || iy >= HFS) continue;
            #pragma unroll
            for (int dx = 0; dx < 3; dx++) {
                int ix = ix0 + dx;
                if (ix < 0 || ix >= HFS) continue;
                const float* p = hs + ((size_t)b * NTOT + 1 + iy * HFS + ix) * CIN;
                int w = dy * 3 + dx;
                v0 += pw[(lane)      * 9 + w] * p[lane];
                v1 += pw[(lane + 32) * 9 + w] * p[lane + 32];
                v2 += pw[(lane + 64) * 9 + w] * p[lane + 64];
            }
        }
    }
    float su  = v0 + v1 + v2;
    float sq  = v0 * v0 + v1 * v1 + v2 * v2;
    #pragma unroll
    for (int o = 16; o; o >>= 1) {
        su += __shfl_xor_sync(0xffffffffu, su, o);
        sq += __shfl_xor_sync(0xffffffffu, sq, o);
    }
    float mean = su * (1.f / 96.f);
    float var  = sq * (1.f / 96.f) - mean * mean;
    float rs   = rsqrtf(var + 1e-5f);
    float* o = out + (size_t)tok * CIN;
    o[lane]      = (v0 - mean) * rs * gam[lane]      + bet[lane];
    o[lane + 32] = (v1 - mean) * rs * gam[lane + 32] + bet[lane + 32];
    o[lane + 64] = (v2 - mean) * rs * gam[lane + 64] + bet[lane + 64];
}

// =====================================================================
// Kernel 2: projection GEMM  Y[M,192] = X[M,96] @ W[96,192] + bias
// 64-row tile per block, 256 threads, per-thread 8x6 register tile
// =====================================================================
#define PROJ_SMEM ((96 * 192 + 64 * 96) * 4)
__global__ __launch_bounds__(256, 1)
void proj_kernel(const float* __restrict__ X,
                 const float* __restrict__ W,
                 const float* __restrict__ bias,
                 float* __restrict__ Y, int M)
{
    extern __shared__ float sh[];
    float* sW = sh;               // 96*192
    float* sX = sh + 96 * 192;    // 64*96
    int tid  = threadIdx.x;
    int row0 = blockIdx.x * 64;

    for (int i = tid; i < 96 * 192; i += 256) sW[i] = W[i];
    for (int i = tid; i < 64 * 96; i += 256) {
        int r = i / 96;
        int gr = row0 + r;
        sX[i] = (gr < M) ? X[(size_t)gr * 96 + (i - r * 96)] : 0.f;
    }
    __syncthreads();

    int ncol = tid & 31;    // cols = ncol + 32*i
    int rg   = tid >> 5;    // rows = rg + 8*j

    float acc[8][6];
    #pragma unroll
    for (int j = 0; j < 8; j++)
        #pragma unroll
        for (int i = 0; i < 6; i++) acc[j][i] = 0.f;

    #pragma unroll 4
    for (int k = 0; k < 96; k++) {
        float wv[6];
        #pragma unroll
        for (int i = 0; i < 6; i++) wv[i] = sW[k * 192 + ncol + 32 * i];
        float xv[8];
        #pragma unroll
        for (int j = 0; j < 8; j++) xv[j] = sX[(rg + 8 * j) * 96 + k];
        #pragma unroll
        for (int j = 0; j < 8; j++)
            #pragma unroll
            for (int i = 0; i < 6; i++) acc[j][i] += xv[j] * wv[i];
    }

    #pragma unroll
    for (int j = 0; j < 8; j++) {
        int gr = row0 + rg + 8 * j;
        if (gr < M) {
            #pragma unroll
            for (int i = 0; i < 6; i++) {
                int n = ncol + 32 * i;
                Y[(size_t)gr * 192 + n] = acc[j][i] + bias[n];
            }
        }
    }
}

// =====================================================================
// Kernel 3: fused attention per (b, head):
//   K (pre-scaled), V resident in smem; per warp 8 q-rows:
//   scores (+decomposed rel-pos bias) -> softmax -> AV -> +residual
// =====================================================================
#define ATTN_SMEM ((197 * 97 + 197 * 96 + 8 * 8 * 96 + 8 * 8 * 197) * 4)
__global__ __launch_bounds__(256, 1)
void attn_kernel(const float* __restrict__ relh,
                 const float* __restrict__ relw,
                 float* __restrict__ out)
{
    extern __shared__ float sh[];
    float* sK = sh;                       // [197][97]  (padded, pre-scaled)
    float* sV = sK + 197 * 97;            // [197][96]
    float* sQ = sV + 197 * 96;            // per-warp [8][96]
    float* sP = sQ + 8 * 8 * 96;          // per-warp [8][197]

    int b    = blockIdx.x >> 1;
    int head = blockIdx.x & 1;
    int tid  = threadIdx.x;

    for (int i = tid; i < NK * HDIM; i += 256) {
        int j = i / HDIM, c = i - j * HDIM;
        size_t g = ((size_t)(b * NK + j)) * COUT + head * HDIM + c;
        sK[j * 97 + c] = SCALE * g_kp[g];
        sV[i]          = g_vp[g];
    }
    __syncthreads();

    int warp = tid >> 5, lane = tid & 31;
    float* qW = sQ + warp * (8 * 96);
    float* pW = sP + warp * (8 * 197);

    for (int base = warp * 8; base < NQ; base += 64) {
        // ---- stage q rows ----
        #pragma unroll
        for (int r = 0; r < 8; r++) {
            int gr = base + r;
            if (gr < NQ) {
                const float* qp = g_qp + ((size_t)(b * NQ + gr)) * COUT + head * HDIM;
                qW[r * 96 + lane]      = qp[lane];
                qW[r * 96 + lane + 32] = qp[lane + 32];
                qW[r * 96 + lane + 64] = qp[lane + 64];
            }
        }
        __syncwarp();

        // ---- decomposed rel-pos dots: lanes 0..13 -> eh(ky), lanes 16..29 -> ew(kx)
        float rel[8];
        #pragma unroll
        for (int r = 0; r < 8; r++) {
            int gr = base + r;
            float a = 0.f;
            if (gr >= 1 && gr < NQ) {
                int qy = (gr - 1) / QH, qx = (gr - 1) - qy * QH;
                const float* R = 0;
                if (lane < 14)                      R = relh + (qy - 2 * lane + 26) * HDIM;
                else if (lane >= 16 && lane < 30)   R = relw + (qx - 2 * (lane - 16) + 26) * HDIM;
                if (R) {
                    const float* q = qW + r * 96;
                    #pragma unroll 8
                    for (int c = 0; c < 96; c++) a += q[c] * __ldg(R + c);
                }
            }
            rel[r] = a;
        }

        // ---- init score accumulators with bias via shuffles ----
        float acc[8][7];
        #pragma unroll
        for (int jj = 0; jj < 7; jj++) {
            int j   = jj * 32 + lane;
            int jm1 = (j >= 1) ? j - 1 : 0;
            int ky  = jm1 / 14;
            int kx  = jm1 - ky * 14;
            if (ky > 15) ky = 15;
            bool ok = (j >= 1 && j < NK);
            #pragma unroll
            for (int r = 0; r < 8; r++) {
                float bh = __shfl_sync(0xffffffffu, rel[r], ky);
                float bw = __shfl_sync(0xffffffffu, rel[r], 16 + kx);
                acc[r][jj] = ok ? (bh + bw) : 0.f;
            }
        }

        const float* kp[7];
        #pragma unroll
        for (int jj = 0; jj < 7; jj++) {
            int j = jj * 32 + lane;
            if (j > NK - 1) j = NK - 1;
            kp[jj] = sK + j * 97;
        }

        // ---- main QK^T dot: 56 fp32 accumulators per lane ----
        #pragma unroll 2
        for (int c = 0; c < 96; c++) {
            float kv[7];
            #pragma unroll
            for (int jj = 0; jj < 7; jj++) kv[jj] = kp[jj][c];
            #pragma unroll
            for (int r = 0; r < 8; r++) {
                float qv = qW[r * 96 + c];
                #pragma unroll
                for (int jj = 0; jj < 7; jj++) acc[r][jj] += qv * kv[jj];
            }
        }

        // ---- softmax per row (registers + warp reductions) ----
        #pragma unroll
        for (int r = 0; r < 8; r++) {
            float m = -1e30f;
            #pragma unroll
            for (int jj = 0; jj < 7; jj++) {
                if (jj * 32 + lane >= NK) acc[r][jj] = -1e30f;
                m = fmaxf(m, acc[r][jj]);
            }
            #pragma unroll
            for (int o = 16; o; o >>= 1) m = fmaxf(m, __shfl_xor_sync(0xffffffffu, m, o));
            float s = 0.f;
            #pragma unroll
            for (int jj = 0; jj < 7; jj++) {
                float e = __expf(acc[r][jj] - m);
                acc[r][jj] = e;
                s += e;
            }
            #pragma unroll
            for (int o = 16; o; o >>= 1) s += __shfl_xor_sync(0xffffffffu, s, o);
            float inv = 1.f / s;
            #pragma unroll
            for (int jj = 0; jj < 7; jj++) {
                int j = jj * 32 + lane;
                if (j < NK) pW[r * 197 + j] = acc[r][jj] * inv;
            }
        }
        __syncwarp();

        // ---- AV: lane owns 3 d-channels x 8 rows ----
        float o0[8], o1[8], o2[8];
        #pragma unroll
        for (int r = 0; r < 8; r++) { o0[r] = 0.f; o1[r] = 0.f; o2[r] = 0.f; }
        #pragma unroll 2
        for (int j = 0; j < NK; j++) {
            float v0 = sV[j * 96 + lane];
            float v1 = sV[j * 96 + lane + 32];
            float v2 = sV[j * 96 + lane + 64];
            #pragma unroll
            for (int r = 0; r < 8; r++) {
                float p = pW[r * 197 + j];
                o0[r] += p * v0; o1[r] += p * v1; o2[r] += p * v2;
            }
        }

        // ---- residual + store ----
        #pragma unroll
        for (int r = 0; r < 8; r++) {
            int gr = base + r;
            if (gr < NQ) {
                float a0 = o0[r], a1 = o1[r], a2 = o2[r];
                if (gr >= 1) {
                    a0 += qW[r * 96 + lane];
                    a1 += qW[r * 96 + lane + 32];
                    a2 += qW[r * 96 + lane + 64];
                }
                float* op = out + ((size_t)(b * NQ + gr)) * COUT + head * HDIM;
                op[lane]      = a0;
                op[lane + 32] = a1;
                op[lane + 64] = a2;
            }
        }
        __syncwarp();
    }
}

// =====================================================================
// launch
// =====================================================================
extern "C" void kernel_launch(void* const* d_in, const int* in_sizes, int n_in,
                              void* d_out, int out_size)
{
    const float* hs    = (const float*)d_in[0];
    const float* Wq    = (const float*)d_in[1];
    const float* bq    = (const float*)d_in[2];
    const float* Wk    = (const float*)d_in[3];
    const float* bk    = (const float*)d_in[4];
    const float* Wv    = (const float*)d_in[5];
    const float* bv    = (const float*)d_in[6];
    const float* pqw   = (const float*)d_in[7];
    const float* pkw   = (const float*)d_in[8];
    const float* pvw   = (const float*)d_in[9];
    const float* gq    = (const float*)d_in[10];
    const float* betaq = (const float*)d_in[11];
    const float* gk    = (const float*)d_in[12];
    const float* betak = (const float*)d_in[13];
    const float* gv    = (const float*)d_in[14];
    const float* betav = (const float*)d_in[15];
    const float* relh  = (const float*)d_in[16];
    const float* relw  = (const float*)d_in[17];
    float* out = (float*)d_out;

    float *qln, *kln, *vln, *qp, *kp, *vp;
    cudaGetSymbolAddress((void**)&qln, g_qln);
    cudaGetSymbolAddress((void**)&kln, g_kln);
    cudaGetSymbolAddress((void**)&vln, g_vln);
    cudaGetSymbolAddress((void**)&qp,  g_qp);
    cudaGetSymbolAddress((void**)&kp,  g_kp);
    cudaGetSymbolAddress((void**)&vp,  g_vp);

    cudaFuncSetAttribute(proj_kernel, cudaFuncAttributeMaxDynamicSharedMemorySize, PROJ_SMEM);
    cudaFuncSetAttribute(attn_kernel, cudaFuncAttributeMaxDynamicSharedMemorySize, ATTN_SMEM);

    // pooling + LN
    pool_ln_kernel<<<(BATCH * NQ + 7) / 8, 256>>>(hs, pqw, gq, betaq, qln, 2, QH, NQ);
    pool_ln_kernel<<<(BATCH * NK + 7) / 8, 256>>>(hs, pkw, gk, betak, kln, 4, KH, NK);
    pool_ln_kernel<<<(BATCH * NK + 7) / 8, 256>>>(hs, pvw, gv, betav, vln, 4, KH, NK);

    // projections
    int Mq = BATCH * NQ;   // 50240
    int Mk = BATCH * NK;   // 12608
    proj_kernel<<<(Mq + 63) / 64, 256, PROJ_SMEM>>>(qln, Wq, bq, qp, Mq);
    proj_kernel<<<(Mk + 63) / 64, 256, PROJ_SMEM>>>(kln, Wk, bk, kp, Mk);
    proj_kernel<<<(Mk + 63) / 64, 256, PROJ_SMEM>>>(vln, Wv, bv, vp, Mk);

    // fused attention
    attn_kernel<<<BATCH * NHEAD, 256, ATTN_SMEM>>>(relh, relw, out);
}

// round 2
// speedup vs baseline: 2.0265x; 2.0265x over previous
#include <cuda_runtime.h>
#include <math.h>

// ---------------- static problem constants ----------------
#define BATCH   64
#define NTOT    3137          // 56*56+1
#define CIN     96
#define COUT    192
#define NHEAD   2
#define HDIM    96
#define HFS     56
#define QH      28
#define KH      14
#define NQ      785           // 28*28+1
#define NK      197           // 14*14+1
#define SCALE   0.10206207261596577f   // 96^-0.5

typedef unsigned long long u64;

__device__ __forceinline__ u64 pk2(float a, float b) {
    u64 r; asm("mov.b64 %0,{%1,%2};" : "=l"(r) : "f"(a), "f"(b)); return r;
}
__device__ __forceinline__ void upk2(u64 v, float& a, float& b) {
    asm("mov.b64 {%0,%1},%2;" : "=f"(a), "=f"(b) : "l"(v));
}
__device__ __forceinline__ u64 ffma2(u64 a, u64 b, u64 c) {
    u64 d; asm("fma.rn.f32x2 %0,%1,%2,%3;" : "=l"(d) : "l"(a), "l"(b), "l"(c)); return d;
}

// ---------------- scratch (device globals; no allocs allowed) ----------------
__device__ float g_qln[BATCH * NQ * CIN];
__device__ float g_kln[BATCH * NK * CIN];
__device__ float g_vln[BATCH * NK * CIN];
__device__ float g_qp [BATCH * NQ * COUT];
__device__ float g_kp [BATCH * NK * COUT];
__device__ float g_vp [BATCH * NK * COUT];

// =====================================================================
// Kernel 1: depthwise 3x3 pool (stride s, pad 1) + LayerNorm over C=96
// =====================================================================
__global__ void pool_ln_kernel(const float* __restrict__ hs,
                               const float* __restrict__ pw,
                               const float* __restrict__ gam,
                               const float* __restrict__ bet,
                               float* __restrict__ out,
                               int stride, int Wout, int ntok)
{
    int warp = threadIdx.x >> 5;
    int lane = threadIdx.x & 31;
    int tok  = blockIdx.x * (blockDim.x >> 5) + warp;
    if (tok >= BATCH * ntok) return;
    int b = tok / ntok;
    int t = tok - b * ntok;

    float v0 = 0.f, v1 = 0.f, v2 = 0.f;
    if (t == 0) {
        const float* p = hs + (size_t)b * NTOT * CIN;
        v0 = p[lane]; v1 = p[lane + 32]; v2 = p[lane + 64];
    } else {
        int s   = t - 1;
        int y   = s / Wout, x = s - y * Wout;
        int iy0 = y * stride - 1, ix0 = x * stride - 1;
        #pragma unroll
        for (int dy = 0; dy < 3; dy++) {
            int iy = iy0 + dy;
            if (iy < 0 || iy >= HFS) continue;
            #pragma unroll
            for (int dx = 0; dx < 3; dx++) {
                int ix = ix0 + dx;
                if (ix < 0 || ix >= HFS) continue;
                const float* p = hs + ((size_t)b * NTOT + 1 + iy * HFS + ix) * CIN;
                int w = dy * 3 + dx;
                v0 += pw[(lane)      * 9 + w] * p[lane];
                v1 += pw[(lane + 32) * 9 + w] * p[lane + 32];
                v2 += pw[(lane + 64) * 9 + w] * p[lane + 64];
            }
        }
    }
    float su  = v0 + v1 + v2;
    float sq  = v0 * v0 + v1 * v1 + v2 * v2;
    #pragma unroll
    for (int o = 16; o; o >>= 1) {
        su += __shfl_xor_sync(0xffffffffu, su, o);
        sq += __shfl_xor_sync(0xffffffffu, sq, o);
    }
    float mean = su * (1.f / 96.f);
    float var  = sq * (1.f / 96.f) - mean * mean;
    float rs   = rsqrtf(var + 1e-5f);
    float* o = out + (size_t)tok * CIN;
    o[lane]      = (v0 - mean) * rs * gam[lane]      + bet[lane];
    o[lane + 32] = (v1 - mean) * rs * gam[lane + 32] + bet[lane + 32];
    o[lane + 64] = (v2 - mean) * rs * gam[lane + 64] + bet[lane + 64];
}

// =====================================================================
// Kernel 2: projection GEMM  Y[M,192] = X[M,96] @ W[96,192] + bias
// FFMA2 packed over row pairs; X staged transposed for LDS.64 pairs.
// =====================================================================
#define PROJ_SMEM ((96 * 192 + 96 * 66) * 4)
__global__ __launch_bounds__(256, 2)
void proj_kernel(const float* __restrict__ X,
                 const float* __restrict__ W,
                 const float* __restrict__ bias,
                 float* __restrict__ Y, int M)
{
    extern __shared__ float sh[];
    float* sW  = sh;              // [96][192]
    float* sXt = sh + 96 * 192;   // [96][66] transposed (k-major, rows contiguous)
    int tid  = threadIdx.x;
    int lane = tid & 31;
    int rg   = tid >> 5;          // warp id: rows rg*8 .. rg*8+7
    int row0 = blockIdx.x * 64;

    for (int i = tid; i < 96 * 192; i += 256) sW[i] = W[i];
    for (int i = tid; i < 64 * 96; i += 256) {
        int r = i / 96, k = i - r * 96;
        int gr = row0 + r;
        sXt[k * 66 + r] = (gr < M) ? X[(size_t)gr * 96 + k] : 0.f;
    }
    __syncthreads();

    u64 acc[4][6];
    #pragma unroll
    for (int i = 0; i < 6; i++) {
        float bv = bias[lane + 32 * i];
        u64 b2 = pk2(bv, bv);
        #pragma unroll
        for (int rp = 0; rp < 4; rp++) acc[rp][i] = b2;
    }

    const float* xw = sXt + rg * 8;
    #pragma unroll 4
    for (int k = 0; k < 96; k++) {
        u64 x01 = *(const u64*)(xw + k * 66);
        u64 x23 = *(const u64*)(xw + k * 66 + 2);
        u64 x45 = *(const u64*)(xw + k * 66 + 4);
        u64 x67 = *(const u64*)(xw + k * 66 + 6);
        #pragma unroll
        for (int i = 0; i < 6; i++) {
            float wv = sW[k * 192 + lane + 32 * i];
            u64 w2 = pk2(wv, wv);
            acc[0][i] = ffma2(x01, w2, acc[0][i]);
            acc[1][i] = ffma2(x23, w2, acc[1][i]);
            acc[2][i] = ffma2(x45, w2, acc[2][i]);
            acc[3][i] = ffma2(x67, w2, acc[3][i]);
        }
    }

    #pragma unroll
    for (int rp = 0; rp < 4; rp++) {
        int gr0 = row0 + rg * 8 + 2 * rp;
        #pragma unroll
        for (int i = 0; i < 6; i++) {
            float a, bv;
            upk2(acc[rp][i], a, bv);
            int n = lane + 32 * i;
            if (gr0 < M)     Y[(size_t)gr0 * 192 + n]       = a;
            if (gr0 + 1 < M) Y[(size_t)(gr0 + 1) * 192 + n] = bv;
        }
    }
}

// =====================================================================
// Kernel 3: fused attention per (b, head).  FFMA2-packed over q-row pairs.
// smem (floats):
//   sK  [197][99]  @ 0        (pre-scaled, odd stride -> conflict-free)
//   sV  [197][96]  @ 19504
//   sQt [96][6] /warp @ 38416 (q transposed: {q[r],q[r+1]} = LDS.64)
//   sPt [197][6]/warp @ 43024 (p transposed: {p[r],p[r+1]} = LDS.64)
// total 52480 floats = 209,920 B
// =====================================================================
#define ATTN_SMEM (52480 * 4)
__global__ __launch_bounds__(256, 1)
void attn_kernel(const float* __restrict__ relh,
                 const float* __restrict__ relw,
                 float* __restrict__ out)
{
    extern __shared__ float sh[];
    float* sK = sh;
    float* sV = sh + 19504;

    int b    = blockIdx.x >> 1;
    int head = blockIdx.x & 1;
    int tid  = threadIdx.x;
    int warp = tid >> 5, lane = tid & 31;

    float* sQt = sh + 38416 + warp * 576;    // [96][6]
    float* sPt = sh + 43024 + warp * 1182;   // [197][6]

    for (int i = tid; i < NK * 96; i += 256) {
        int j = i / 96, c = i - j * 96;
        size_t g = ((size_t)(b * NK + j)) * COUT + head * HDIM + c;
        sK[j * 99 + c] = SCALE * g_kp[g];
        sV[i]          = g_vp[g];
    }
    __syncthreads();

    // per-lane K row offsets and bias shuffle indices
    int kb[7], kyv[7], kxv[7];
    #pragma unroll
    for (int jj = 0; jj < 7; jj++) {
        int j  = jj * 32 + lane;
        int jc = (j > 196) ? 196 : j;
        kb[jj] = jc * 99;
        int jm = (j >= 1) ? j - 1 : 0;
        int ky = jm / 14;
        if (ky > 13) ky = 13;
        kyv[jj] = ky;
        kxv[jj] = 16 + (jm % 14);
    }

    bool isH = (lane < 14);
    bool isW = (lane >= 16 && lane < 30);
    int  lrel = isH ? lane : (lane - 16);
    const float* Rtab = isH ? relh : relw;

    for (int base = warp * 4; base < NQ; base += 32) {
        // ---- stage q rows (transposed) ----
        #pragma unroll
        for (int r = 0; r < 4; r++) {
            int gr = base + r;
            int cg = (gr < NQ) ? gr : 0;
            const float* qp = g_qp + ((size_t)(b * NQ + cg)) * COUT + head * HDIM;
            sQt[lane * 6 + r]        = qp[lane];
            sQt[(lane + 32) * 6 + r] = qp[lane + 32];
            sQt[(lane + 64) * 6 + r] = qp[lane + 64];
        }
        __syncwarp();

        // ---- decomposed rel-pos dots, packed over row pairs ----
        float rel_s[4];
        #pragma unroll
        for (int rp = 0; rp < 2; rp++) {
            int ga = base + 2 * rp, gb = ga + 1;
            const float* Ra = Rtab;
            const float* Rb = Rtab;
            bool va = false, vb = false;
            if (ga >= 1 && ga < NQ && (isH || isW)) {
                int s = ga - 1; int qy = s / QH, qx = s - qy * QH;
                Ra = Rtab + ((isH ? qy : qx) - 2 * lrel + 26) * 96;
                va = true;
            }
            if (gb >= 1 && gb < NQ && (isH || isW)) {
                int s = gb - 1; int qy = s / QH, qx = s - qy * QH;
                Rb = Rtab + ((isH ? qy : qx) - 2 * lrel + 26) * 96;
                vb = true;
            }
            u64 r0 = 0, r1 = 0;
            #pragma unroll 4
            for (int c4 = 0; c4 < 24; c4++) {
                float4 A = __ldg(reinterpret_cast<const float4*>(Ra) + c4);
                float4 Bv = __ldg(reinterpret_cast<const float4*>(Rb) + c4);
                const float* qb = sQt + (c4 * 4) * 6 + 2 * rp;
                r0 = ffma2(*(const u64*)(qb),      pk2(A.x, Bv.x), r0);
                r1 = ffma2(*(const u64*)(qb + 6),  pk2(A.y, Bv.y), r1);
                r0 = ffma2(*(const u64*)(qb + 12), pk2(A.z, Bv.z), r0);
                r1 = ffma2(*(const u64*)(qb + 18), pk2(A.w, Bv.w), r1);
            }
            float a0, a1, b0, b1;
            upk2(r0, a0, b0); upk2(r1, a1, b1);
            rel_s[2 * rp]     = va ? (a0 + a1) : 0.f;
            rel_s[2 * rp + 1] = vb ? (b0 + b1) : 0.f;
        }

        // ---- init score accumulators with bias via shuffles ----
        u64 acc[2][7];
        #pragma unroll
        for (int jj = 0; jj < 7; jj++) {
            int j = jj * 32 + lane;
            float bb[4];
            #pragma unroll
            for (int r = 0; r < 4; r++) {
                float bh = __shfl_sync(0xffffffffu, rel_s[r], kyv[jj]);
                float bw = __shfl_sync(0xffffffffu, rel_s[r], kxv[jj]);
                bb[r] = (j >= 1) ? (bh + bw) : 0.f;
            }
            acc[0][jj] = pk2(bb[0], bb[1]);
            acc[1][jj] = pk2(bb[2], bb[3]);
        }

        // ---- main QK^T: FFMA2 over row pairs ----
        #pragma unroll 4
        for (int c = 0; c < 96; c++) {
            u64 q01 = *(const u64*)(sQt + c * 6);
            u64 q23 = *(const u64*)(sQt + c * 6 + 2);
            #pragma unroll
            for (int jj = 0; jj < 7; jj++) {
                float kv = sK[kb[jj] + c];
                u64 k2 = pk2(kv, kv);
                acc[0][jj] = ffma2(q01, k2, acc[0][jj]);
                acc[1][jj] = ffma2(q23, k2, acc[1][jj]);
            }
        }

        // ---- softmax (two rows at a time) + store P transposed ----
        #pragma unroll
        for (int rp = 0; rp < 2; rp++) {
            float x0[7], x1[7];
            #pragma unroll
            for (int jj = 0; jj < 7; jj++) {
                upk2(acc[rp][jj], x0[jj], x1[jj]);
            }
            if (lane >= 5) { x0[6] = -1e30f; x1[6] = -1e30f; }
            float m0 = -1e30f, m1 = -1e30f;
            #pragma unroll
            for (int jj = 0; jj < 7; jj++) {
                m0 = fmaxf(m0, x0[jj]); m1 = fmaxf(m1, x1[jj]);
            }
            #pragma unroll
            for (int o = 16; o; o >>= 1) {
                m0 = fmaxf(m0, __shfl_xor_sync(0xffffffffu, m0, o));
                m1 = fmaxf(m1, __shfl_xor_sync(0xffffffffu, m1, o));
            }
            float s0 = 0.f, s1 = 0.f;
            #pragma unroll
            for (int jj = 0; jj < 7; jj++) {
                x0[jj] = __expf(x0[jj] - m0); s0 += x0[jj];
                x1[jj] = __expf(x1[jj] - m1); s1 += x1[jj];
            }
            #pragma unroll
            for (int o = 16; o; o >>= 1) {
                s0 += __shfl_xor_sync(0xffffffffu, s0, o);
                s1 += __shfl_xor_sync(0xffffffffu, s1, o);
            }
            float i0 = 1.f / s0, i1 = 1.f / s1;
            #pragma unroll
            for (int jj = 0; jj < 7; jj++) {
                int j = jj * 32 + lane;
                if (j < NK)
                    *(u64*)(sPt + j * 6 + 2 * rp) = pk2(x0[jj] * i0, x1[jj] * i1);
            }
        }
        __syncwarp();

        // ---- AV: FFMA2 over row pairs, p-pairs via LDS.64 broadcast ----
        u64 o2[2][3];
        #pragma unroll
        for (int rp = 0; rp < 2; rp++)
            #pragma unroll
            for (int i = 0; i < 3; i++) o2[rp][i] = 0;

        #pragma unroll 2
        for (int j = 0; j < NK; j++) {
            u64 p01 = *(const u64*)(sPt + j * 6);
            u64 p23 = *(const u64*)(sPt + j * 6 + 2);
            float v0 = sV[j * 96 + lane];
            float v1 = sV[j * 96 + lane + 32];
            float v2 = sV[j * 96 + lane + 64];
            u64 w0 = pk2(v0, v0), w1 = pk2(v1, v1), w2 = pk2(v2, v2);
            o2[0][0] = ffma2(p01, w0, o2[0][0]);
            o2[1][0] = ffma2(p23, w0, o2[1][0]);
            o2[0][1] = ffma2(p01, w1, o2[0][1]);
            o2[1][1] = ffma2(p23, w1, o2[1][1]);
            o2[0][2] = ffma2(p01, w2, o2[0][2]);
            o2[1][2] = ffma2(p23, w2, o2[1][2]);
        }

        // ---- residual + store ----
        #pragma unroll
        for (int rp = 0; rp < 2; rp++) {
            float a0, b0, a1, b1, a2, b2;
            upk2(o2[rp][0], a0, b0);
            upk2(o2[rp][1], a1, b1);
            upk2(o2[rp][2], a2, b2);
            int g0 = base + 2 * rp;
            if (g0 < NQ) {
                float r0 = a0, r1 = a1, r2 = a2;
                if (g0 >= 1) {
                    r0 += sQt[lane * 6 + 2 * rp];
                    r1 += sQt[(lane + 32) * 6 + 2 * rp];
                    r2 += sQt[(lane + 64) * 6 + 2 * rp];
                }
                float* op = out + ((size_t)(b * NQ + g0)) * COUT + head * HDIM;
                op[lane] = r0; op[lane + 32] = r1; op[lane + 64] = r2;
            }
            int g1 = g0 + 1;
            if (g1 < NQ) {
                float r0 = b0, r1 = b1, r2 = b2;
                if (g1 >= 1) {
                    r0 += sQt[lane * 6 + 2 * rp + 1];
                    r1 += sQt[(lane + 32) * 6 + 2 * rp + 1];
                    r2 += sQt[(lane + 64) * 6 + 2 * rp + 1];
                }
                float* op = out + ((size_t)(b * NQ + g1)) * COUT + head * HDIM;
                op[lane] = r0; op[lane + 32] = r1; op[lane + 64] = r2;
            }
        }
        __syncwarp();
    }
}

// =====================================================================
// launch
// =====================================================================
extern "C" void kernel_launch(void* const* d_in, const int* in_sizes, int n_in,
                              void* d_out, int out_size)
{
    const float* hs    = (const float*)d_in[0];
    const float* Wq    = (const float*)d_in[1];
    const float* bq    = (const float*)d_in[2];
    const float* Wk    = (const float*)d_in[3];
    const float* bk    = (const float*)d_in[4];
    const float* Wv    = (const float*)d_in[5];
    const float* bv    = (const float*)d_in[6];
    const float* pqw   = (const float*)d_in[7];
    const float* pkw   = (const float*)d_in[8];
    const float* pvw   = (const float*)d_in[9];
    const float* gq    = (const float*)d_in[10];
    const float* betaq = (const float*)d_in[11];
    const float* gk    = (const float*)d_in[12];
    const float* betak = (const float*)d_in[13];
    const float* gv    = (const float*)d_in[14];
    const float* betav = (const float*)d_in[15];
    const float* relh  = (const float*)d_in[16];
    const float* relw  = (const float*)d_in[17];
    float* out = (float*)d_out;

    float *qln, *kln, *vln, *qp, *kp, *vp;
    cudaGetSymbolAddress((void**)&qln, g_qln);
    cudaGetSymbolAddress((void**)&kln, g_kln);
    cudaGetSymbolAddress((void**)&vln, g_vln);
    cudaGetSymbolAddress((void**)&qp,  g_qp);
    cudaGetSymbolAddress((void**)&kp,  g_kp);
    cudaGetSymbolAddress((void**)&vp,  g_vp);

    cudaFuncSetAttribute(proj_kernel, cudaFuncAttributeMaxDynamicSharedMemorySize, PROJ_SMEM);
    cudaFuncSetAttribute(attn_kernel, cudaFuncAttributeMaxDynamicSharedMemorySize, ATTN_SMEM);

    // pooling + LN
    pool_ln_kernel<<<(BATCH * NQ + 7) / 8, 256>>>(hs, pqw, gq, betaq, qln, 2, QH, NQ);
    pool_ln_kernel<<<(BATCH * NK + 7) / 8, 256>>>(hs, pkw, gk, betak, kln, 4, KH, NK);
    pool_ln_kernel<<<(BATCH * NK + 7) / 8, 256>>>(hs, pvw, gv, betav, vln, 4, KH, NK);

    // projections
    int Mq = BATCH * NQ;   // 50240
    int Mk = BATCH * NK;   // 12608
    proj_kernel<<<(Mq + 63) / 64, 256, PROJ_SMEM>>>(qln, Wq, bq, qp, Mq);
    proj_kernel<<<(Mk + 63) / 64, 256, PROJ_SMEM>>>(kln, Wk, bk, kp, Mk);
    proj_kernel<<<(Mk + 63) / 64, 256, PROJ_SMEM>>>(vln, Wv, bv, vp, Mk);

    // fused attention
    attn_kernel<<<BATCH * NHEAD, 256, ATTN_SMEM>>>(relh, relw, out);
}

// round 4
// speedup vs baseline: 3.8866x; 1.9179x over previous
#include <cuda_runtime.h>
#include <cuda_bf16.h>
#include <math.h>

// ---------------- static problem constants ----------------
#define BATCH   64
#define NTOT    3137          // 56*56+1
#define CIN     96
#define COUT    192
#define NHEAD   2
#define HDIM    96
#define HFS     56
#define QH      28
#define KH      14
#define NQ      785           // 28*28+1
#define NK      197           // 14*14+1
#define SCALE   0.10206207261596577f   // 96^-0.5

typedef unsigned long long u64;
typedef unsigned int u32;

__device__ __forceinline__ u64 pk2(float a, float b) {
    u64 r; asm("mov.b64 %0,{%1,%2};" : "=l"(r) : "f"(a), "f"(b)); return r;
}
__device__ __forceinline__ void upk2(u64 v, float& a, float& b) {
    asm("mov.b64 {%0,%1},%2;" : "=f"(a), "=f"(b) : "l"(v));
}
__device__ __forceinline__ u64 ffma2(u64 a, u64 b, u64 c) {
    u64 d; asm("fma.rn.f32x2 %0,%1,%2,%3;" : "=l"(d) : "l"(a), "l"(b), "l"(c)); return d;
}
// pack two fp32 -> bf16x2 (lo in low half, hi in high half)
__device__ __forceinline__ u32 bf2(float lo, float hi) {
    u32 r; asm("cvt.rn.bf16x2.f32 %0, %1, %2;" : "=r"(r) : "f"(hi), "f"(lo)); return r;
}
// single fp32 -> bf16 in low 16 bits
__device__ __forceinline__ unsigned short bf1(float v) {
    unsigned short r; asm("cvt.rn.bf16.f32 %0, %1;" : "=h"(r) : "f"(v)); return r;
}
__device__ __forceinline__ void mma_bf16(float* d, const u32* a, u32 b0, u32 b1) {
    asm volatile("mma.sync.aligned.m16n8k16.row.col.f32.bf16.bf16.f32 "
        "{%0,%1,%2,%3},{%4,%5,%6,%7},{%8,%9},{%0,%1,%2,%3};"
        : "+f"(d[0]), "+f"(d[1]), "+f"(d[2]), "+f"(d[3])
        : "r"(a[0]), "r"(a[1]), "r"(a[2]), "r"(a[3]), "r"(b0), "r"(b1));
}

// ---------------- scratch (device globals) ----------------
__device__ float g_qln[BATCH * NQ * CIN];
__device__ float g_kln[BATCH * NK * CIN];
__device__ float g_vln[BATCH * NK * CIN];
__device__ float g_qp [BATCH * NQ * COUT];
__device__ float g_kp [BATCH * NK * COUT];
__device__ float g_vp [BATCH * NK * COUT];
__device__ float g_ehw[BATCH * NHEAD * 784 * 28];   // per (b,h,spatial q): eh[14] | ew[14]

// =====================================================================
// Kernel 1: depthwise 3x3 pool (stride s, pad 1) + LayerNorm over C=96
// =====================================================================
__global__ void pool_ln_kernel(const float* __restrict__ hs,
                               const float* __restrict__ pw,
                               const float* __restrict__ gam,
                               const float* __restrict__ bet,
                               float* __restrict__ out,
                               int stride, int Wout, int ntok)
{
    int warp = threadIdx.x >> 5;
    int lane = threadIdx.x & 31;
    int tok  = blockIdx.x * (blockDim.x >> 5) + warp;
    if (tok >= BATCH * ntok) return;
    int b = tok / ntok;
    int t = tok - b * ntok;

    float v0 = 0.f, v1 = 0.f, v2 = 0.f;
    if (t == 0) {
        const float* p = hs + (size_t)b * NTOT * CIN;
        v0 = p[lane]; v1 = p[lane + 32]; v2 = p[lane + 64];
    } else {
        int s   = t - 1;
        int y   = s / Wout, x = s - y * Wout;
        int iy0 = y * stride - 1, ix0 = x * stride - 1;
        #pragma unroll
        for (int dy = 0; dy < 3; dy++) {
            int iy = iy0 + dy;
            if (iy < 0 || iy >= HFS) continue;
            #pragma unroll
            for (int dx = 0; dx < 3; dx++) {
                int ix = ix0 + dx;
                if (ix < 0 || ix >= HFS) continue;
                const float* p = hs + ((size_t)b * NTOT + 1 + iy * HFS + ix) * CIN;
                int w = dy * 3 + dx;
                v0 += pw[(lane)      * 9 + w] * p[lane];
                v1 += pw[(lane + 32) * 9 + w] * p[lane + 32];
                v2 += pw[(lane + 64) * 9 + w] * p[lane + 64];
            }
        }
    }
    float su  = v0 + v1 + v2;
    float sq  = v0 * v0 + v1 * v1 + v2 * v2;
    #pragma unroll
    for (int o = 16; o; o >>= 1) {
        su += __shfl_xor_sync(0xffffffffu, su, o);
        sq += __shfl_xor_sync(0xffffffffu, sq, o);
    }
    float mean = su * (1.f / 96.f);
    float var  = sq * (1.f / 96.f) - mean * mean;
    float rs   = rsqrtf(var + 1e-5f);
    float* o = out + (size_t)tok * CIN;
    o[lane]      = (v0 - mean) * rs * gam[lane]      + bet[lane];
    o[lane + 32] = (v1 - mean) * rs * gam[lane + 32] + bet[lane + 32];
    o[lane + 64] = (v2 - mean) * rs * gam[lane + 64] + bet[lane + 64];
}

// =====================================================================
// Kernel 2: projection GEMM  Y[M,192] = X[M,96] @ W[96,192] + bias
// (fp32 FFMA2 — q feeds the residual so precision must stay fp32)
// =====================================================================
#define PROJ_SMEM ((96 * 192 + 96 * 66) * 4)
__global__ __launch_bounds__(256, 2)
void proj_kernel(const float* __restrict__ X,
                 const float* __restrict__ W,
                 const float* __restrict__ bias,
                 float* __restrict__ Y, int M)
{
    extern __shared__ float sh[];
    float* sW  = sh;
    float* sXt = sh + 96 * 192;
    int tid  = threadIdx.x;
    int lane = tid & 31;
    int rg   = tid >> 5;
    int row0 = blockIdx.x * 64;

    for (int i = tid; i < 96 * 192; i += 256) sW[i] = W[i];
    for (int i = tid; i < 64 * 96; i += 256) {
        int r = i / 96, k = i - r * 96;
        int gr = row0 + r;
        sXt[k * 66 + r] = (gr < M) ? X[(size_t)gr * 96 + k] : 0.f;
    }
    __syncthreads();

    u64 acc[4][6];
    #pragma unroll
    for (int i = 0; i < 6; i++) {
        float bv = bias[lane + 32 * i];
        u64 b2 = pk2(bv, bv);
        #pragma unroll
        for (int rp = 0; rp < 4; rp++) acc[rp][i] = b2;
    }

    const float* xw = sXt + rg * 8;
    #pragma unroll 4
    for (int k = 0; k < 96; k++) {
        u64 x01 = *(const u64*)(xw + k * 66);
        u64 x23 = *(const u64*)(xw + k * 66 + 2);
        u64 x45 = *(const u64*)(xw + k * 66 + 4);
        u64 x67 = *(const u64*)(xw + k * 66 + 6);
        #pragma unroll
        for (int i = 0; i < 6; i++) {
            float wv = sW[k * 192 + lane + 32 * i];
            u64 w2 = pk2(wv, wv);
            acc[0][i] = ffma2(x01, w2, acc[0][i]);
            acc[1][i] = ffma2(x23, w2, acc[1][i]);
            acc[2][i] = ffma2(x45, w2, acc[2][i]);
            acc[3][i] = ffma2(x67, w2, acc[3][i]);
        }
    }

    #pragma unroll
    for (int rp = 0; rp < 4; rp++) {
        int gr0 = row0 + rg * 8 + 2 * rp;
        #pragma unroll
        for (int i = 0; i < 6; i++) {
            float a, bv;
            upk2(acc[rp][i], a, bv);
            int n = lane + 32 * i;
            if (gr0 < M)     Y[(size_t)gr0 * 192 + n]       = a;
            if (gr0 + 1 < M) Y[(size_t)(gr0 + 1) * 192 + n] = bv;
        }
    }
}

// =====================================================================
// Kernel 2b: rel-pos bias table.
//   g_ehw[bh, s, 0:14]  = eh(ky) = q[b,h,s+1,:] . Rh[qy-2ky+26,:]
//   g_ehw[bh, s, 14:28] = ew(kx) = q . Rw[qx-2kx+26,:]
// =====================================================================
#define REL_SMEM ((2 * 55 * 98 + 64 * 96) * 4)
__global__ __launch_bounds__(256, 1)
void rel_kernel(const float* __restrict__ relh,
                const float* __restrict__ relw)
{
    extern __shared__ float sh[];
    float* sR = sh;                 // [2][55][98]
    float* sQ = sh + 2 * 55 * 98;   // [64][96]
    int tid = threadIdx.x;
    int row0 = blockIdx.x * 64;
    const int TOTAL = BATCH * NHEAD * 784;

    for (int i = tid; i < 2 * 55 * 96; i += 256) {
        int tab = i / (55 * 96);
        int rem = i - tab * (55 * 96);
        int r = rem / 96, c = rem - r * 96;
        sR[(tab * 55 + r) * 98 + c] = tab ? relw[r * 96 + c] : relh[r * 96 + c];
    }
    for (int i = tid; i < 64 * 96; i += 256) {
        int lr = i / 96, c = i - lr * 96;
        int rid = row0 + lr;
        float v = 0.f;
        if (rid < TOTAL) {
            int bh = rid / 784, s = rid - bh * 784;
            int b = bh >> 1, h = bh & 1;
            v = g_qp[((size_t)b * NQ + s + 1) * COUT + h * HDIM + c];
        }
        sQ[lr * 96 + c] = v;
    }
    __syncthreads();

    int warp = tid >> 5, lane = tid & 31;
    bool isH = (lane < 14);
    bool isW = (lane >= 16 && lane < 30);
    int  kk  = isH ? lane : (lane - 16);

    #pragma unroll
    for (int rr = 0; rr < 8; rr++) {
        int lr = warp * 8 + rr;
        int rid = row0 + lr;
        if (rid >= TOTAL) continue;
        int s = rid % 784;
        int qy = s / QH, qx = s - qy * QH;
        int coord = isH ? qy : qx;
        int idx = coord - 2 * kk + 26;
        int tab = isH ? 0 : 1;
        if (!(isH || isW)) idx = 0;
        const float* R = sR + (tab * 55 + idx) * 98;
        const float* q = sQ + lr * 96;
        u64 a2 = 0;
        #pragma unroll 8
        for (int c2 = 0; c2 < 48; c2++)
            a2 = ffma2(*(const u64*)(q + 2 * c2), *(const u64*)(R + 2 * c2), a2);
        float a, b2v;
        upk2(a2, a, b2v);
        if (isH || isW)
            g_ehw[(size_t)rid * 28 + tab * 14 + kk] = a + b2v;
    }
}

// =====================================================================
// Kernel 3: fused attention per (b, head) with bf16 mma.sync tensor cores.
// smem (bytes):
//   sK   [200][104] bf16  @ 0        (pre-scaled K, rows>=197 zero)
//   sVt  [96][216]  bf16  @ 41600    (V transposed, cols>=197 zero)
//   sP   8w x [16][216] bf16 @ 83072 (probabilities, zero-initialized)
//   sEHW 8w x [16][28] fp32 @ 138368 (staged rel bias rows)
// total 152704
// =====================================================================
#define SK_OFF   0
#define SVT_OFF  41600
#define SP_OFF   83072
#define SEHW_OFF 138368
#define ATTN_SMEM 152704

__global__ __launch_bounds__(256, 1)
void attn_kernel(float* __restrict__ out)
{
    extern __shared__ char smem[];
    char* sK  = smem + SK_OFF;
    char* sVt = smem + SVT_OFF;
    int b    = blockIdx.x >> 1;
    int head = blockIdx.x & 1;
    int tid  = threadIdx.x;
    int warp = tid >> 5, lane = tid & 31;
    int g = lane >> 2, t = lane & 3;

    u32*   psP  = (u32*)(smem + SP_OFF + warp * 6912);     // word = bf16 pair
    float* sEHW = (float*)(smem + SEHW_OFF) + warp * 448;  // [16][28]

    // ---- stage K (scaled, bf16) ----
    for (int i = tid; i < 200 * 96; i += 256) {
        int j = i / 96, c = i - j * 96;
        float v = 0.f;
        if (j < NK) v = SCALE * g_kp[((size_t)b * NK + j) * COUT + head * HDIM + c];
        *(unsigned short*)(sK + (j * 104 + c) * 2) = bf1(v);
    }
    // ---- stage V transposed (bf16) ----
    for (int i = tid; i < 96 * 216; i += 256) {
        int c = i / 216, j = i - c * 216;
        float v = 0.f;
        if (j < NK) v = g_vp[((size_t)b * NK + j) * COUT + head * HDIM + c];
        *(unsigned short*)(sVt + (c * 216 + j) * 2) = bf1(v);
    }
    // ---- zero P ----
    for (int i = tid; i < 55296 / 4; i += 256)
        ((u32*)(smem + SP_OFF))[i] = 0;
    __syncthreads();

    const float* qbase = g_qp + (size_t)b * NQ * COUT + head * HDIM;
    int bh = b * 2 + head;

    for (int tile = warp; tile < 50; tile += 8) {
        int q0 = tile * 16;
        int r0 = q0 + g, r1 = q0 + g + 8;
        int r0c = (r0 < NQ) ? r0 : NQ - 1;
        int r1c = (r1 < NQ) ? r1 : NQ - 1;

        // ---- stage rel bias rows for this tile ----
        for (int idx = lane; idx < 448; idx += 32) {
            int r = idx / 28, k = idx - r * 28;
            int gr = q0 + r;
            float v = 0.f;
            if (gr >= 1 && gr < NQ)
                v = g_ehw[((size_t)bh * 784 + gr - 1) * 28 + k];
            sEHW[idx] = v;
        }

        // ---- load Q A-fragments (bf16) ----
        const float* q_r0 = qbase + (size_t)r0c * COUT;
        const float* q_r1 = qbase + (size_t)r1c * COUT;
        u32 a[6][4];
        #pragma unroll
        for (int ks = 0; ks < 6; ks++) {
            float2 x0 = *(const float2*)(q_r0 + 16 * ks + 2 * t);
            float2 x1 = *(const float2*)(q_r1 + 16 * ks + 2 * t);
            float2 x2 = *(const float2*)(q_r0 + 16 * ks + 2 * t + 8);
            float2 x3 = *(const float2*)(q_r1 + 16 * ks + 2 * t + 8);
            a[ks][0] = bf2(x0.x, x0.y);
            a[ks][1] = bf2(x1.x, x1.y);
            a[ks][2] = bf2(x2.x, x2.y);
            a[ks][3] = bf2(x3.x, x3.y);
        }
        __syncwarp();

        // ---- QK^T: 25 n-tiles x 6 k-steps ----
        float acc[25][4];
        #pragma unroll
        for (int nt = 0; nt < 25; nt++)
            #pragma unroll
            for (int i = 0; i < 4; i++) acc[nt][i] = 0.f;

        #pragma unroll
        for (int nt = 0; nt < 25; nt++) {
            const char* kb = sK + ((8 * nt + g) * 104 + 2 * t) * 2;
            #pragma unroll
            for (int ks = 0; ks < 6; ks++) {
                u32 b0 = *(const u32*)(kb + 16 * ks * 2);
                u32 b1 = *(const u32*)(kb + (16 * ks + 8) * 2);
                mma_bf16(acc[nt], a[ks], b0, b1);
            }
        }

        // ---- bias + mask + softmax (rows g and g+8 in registers) ----
        float mlo = -1e30f, mhi = -1e30f;
        const float* elo = sEHW + g * 28;
        const float* ehi = sEHW + (g + 8) * 28;
        #pragma unroll
        for (int nt = 0; nt < 25; nt++) {
            #pragma unroll
            for (int jo = 0; jo < 2; jo++) {
                int j = 8 * nt + 2 * t + jo;
                if (j >= NK) {
                    acc[nt][jo]     = -1e30f;
                    acc[nt][2 + jo] = -1e30f;
                } else if (j >= 1) {
                    int ky = (j - 1) / 14;
                    int kx = (j - 1) - ky * 14;
                    acc[nt][jo]     += elo[ky] + elo[14 + kx];
                    acc[nt][2 + jo] += ehi[ky] + ehi[14 + kx];
                }
                mlo = fmaxf(mlo, acc[nt][jo]);
                mhi = fmaxf(mhi, acc[nt][2 + jo]);
            }
        }
        mlo = fmaxf(mlo, __shfl_xor_sync(0xffffffffu, mlo, 1));
        mlo = fmaxf(mlo, __shfl_xor_sync(0xffffffffu, mlo, 2));
        mhi = fmaxf(mhi, __shfl_xor_sync(0xffffffffu, mhi, 1));
        mhi = fmaxf(mhi, __shfl_xor_sync(0xffffffffu, mhi, 2));

        float slo = 0.f, shi = 0.f;
        #pragma unroll
        for (int nt = 0; nt < 25; nt++) {
            #pragma unroll
            for (int jo = 0; jo < 2; jo++) {
                float e0 = __expf(acc[nt][jo] - mlo);
                float e1 = __expf(acc[nt][2 + jo] - mhi);
                acc[nt][jo] = e0;     slo += e0;
                acc[nt][2 + jo] = e1; shi += e1;
            }
        }
        slo += __shfl_xor_sync(0xffffffffu, slo, 1);
        slo += __shfl_xor_sync(0xffffffffu, slo, 2);
        shi += __shfl_xor_sync(0xffffffffu, shi, 1);
        shi += __shfl_xor_sync(0xffffffffu, shi, 2);
        float ilo = 1.f / slo, ihi = 1.f / shi;

        #pragma unroll
        for (int nt = 0; nt < 25; nt++) {
            psP[g * 108 + 4 * nt + t]       = bf2(acc[nt][0] * ilo, acc[nt][1] * ilo);
            psP[(g + 8) * 108 + 4 * nt + t] = bf2(acc[nt][2] * ihi, acc[nt][3] * ihi);
        }
        __syncwarp();

        // ---- AV: 13 k-steps x 12 n-tiles ----
        float o[12][4];
        #pragma unroll
        for (int nt = 0; nt < 12; nt++)
            #pragma unroll
            for (int i = 0; i < 4; i++) o[nt][i] = 0.f;

        #pragma unroll
        for (int ks = 0; ks < 13; ks++) {
            u32 pa[4];
            pa[0] = psP[g * 108 + 8 * ks + t];
            pa[1] = psP[(g + 8) * 108 + 8 * ks + t];
            pa[2] = psP[g * 108 + 8 * ks + t + 4];
            pa[3] = psP[(g + 8) * 108 + 8 * ks + t + 4];
            #pragma unroll
            for (int nt = 0; nt < 12; nt++) {
                const char* vb = sVt + ((8 * nt + g) * 216 + 16 * ks + 2 * t) * 2;
                u32 b0 = *(const u32*)(vb);
                u32 b1 = *(const u32*)(vb + 16);
                mma_bf16(o[nt], pa, b0, b1);
            }
        }

        // ---- residual + store ----
        float* obase = out + (size_t)b * NQ * COUT + head * HDIM;
        #pragma unroll
        for (int nt = 0; nt < 12; nt++) {
            int c = 8 * nt + 2 * t;
            if (r0 < NQ) {
                float2 r = make_float2(o[nt][0], o[nt][1]);
                if (r0 >= 1) {
                    float2 q = *(const float2*)(qbase + (size_t)r0 * COUT + c);
                    r.x += q.x; r.y += q.y;
                }
                *(float2*)(obase + (size_t)r0 * COUT + c) = r;
            }
            if (r1 < NQ) {
                float2 r = make_float2(o[nt][2], o[nt][3]);
                if (r1 >= 1) {
                    float2 q = *(const float2*)(qbase + (size_t)r1 * COUT + c);
                    r.x += q.x; r.y += q.y;
                }
                *(float2*)(obase + (size_t)r1 * COUT + c) = r;
            }
        }
        __syncwarp();
    }
}

// =====================================================================
// launch
// =====================================================================
extern "C" void kernel_launch(void* const* d_in, const int* in_sizes, int n_in,
                              void* d_out, int out_size)
{
    const float* hs    = (const float*)d_in[0];
    const float* Wq    = (const float*)d_in[1];
    const float* bq    = (const float*)d_in[2];
    const float* Wk    = (const float*)d_in[3];
    const float* bk    = (const float*)d_in[4];
    const float* Wv    = (const float*)d_in[5];
    const float* bv    = (const float*)d_in[6];
    const float* pqw   = (const float*)d_in[7];
    const float* pkw   = (const float*)d_in[8];
    const float* pvw   = (const float*)d_in[9];
    const float* gq    = (const float*)d_in[10];
    const float* betaq = (const float*)d_in[11];
    const float* gk    = (const float*)d_in[12];
    const float* betak = (const float*)d_in[13];
    const float* gv    = (const float*)d_in[14];
    const float* betav = (const float*)d_in[15];
    const float* relh  = (const float*)d_in[16];
    const float* relw  = (const float*)d_in[17];
    float* out = (float*)d_out;

    float *qln, *kln, *vln, *qp, *kp, *vp;
    cudaGetSymbolAddress((void**)&qln, g_qln);
    cudaGetSymbolAddress((void**)&kln, g_kln);
    cudaGetSymbolAddress((void**)&vln, g_vln);
    cudaGetSymbolAddress((void**)&qp,  g_qp);
    cudaGetSymbolAddress((void**)&kp,  g_kp);
    cudaGetSymbolAddress((void**)&vp,  g_vp);

    cudaFuncSetAttribute(proj_kernel, cudaFuncAttributeMaxDynamicSharedMemorySize, PROJ_SMEM);
    cudaFuncSetAttribute(rel_kernel,  cudaFuncAttributeMaxDynamicSharedMemorySize, REL_SMEM);
    cudaFuncSetAttribute(attn_kernel, cudaFuncAttributeMaxDynamicSharedMemorySize, ATTN_SMEM);

    // pooling + LN
    pool_ln_kernel<<<(BATCH * NQ + 7) / 8, 256>>>(hs, pqw, gq, betaq, qln, 2, QH, NQ);
    pool_ln_kernel<<<(BATCH * NK + 7) / 8, 256>>>(hs, pkw, gk, betak, kln, 4, KH, NK);
    pool_ln_kernel<<<(BATCH * NK + 7) / 8, 256>>>(hs, pvw, gv, betav, vln, 4, KH, NK);

    // projections (fp32)
    int Mq = BATCH * NQ;
    int Mk = BATCH * NK;
    proj_kernel<<<(Mq + 63) / 64, 256, PROJ_SMEM>>>(qln, Wq, bq, qp, Mq);
    proj_kernel<<<(Mk + 63) / 64, 256, PROJ_SMEM>>>(kln, Wk, bk, kp, Mk);
    proj_kernel<<<(Mk + 63) / 64, 256, PROJ_SMEM>>>(vln, Wv, bv, vp, Mk);

    // rel-pos bias table (needs q projection)
    rel_kernel<<<(BATCH * NHEAD * 784 + 63) / 64, 256, REL_SMEM>>>(relh, relw);

    // fused tensor-core attention
    attn_kernel<<<BATCH * NHEAD, 256, ATTN_SMEM>>>(out);
}

// round 5
// speedup vs baseline: 4.0417x; 1.0399x over previous
#include <cuda_runtime.h>
#include <cuda_bf16.h>
#include <math.h>

// ---------------- static problem constants ----------------
#define BATCH   64
#define NTOT    3137          // 56*56+1
#define CIN     96
#define COUT    192
#define NHEAD   2
#define HDIM    96
#define HFS     56
#define QH      28
#define KH      14
#define NQ      785           // 28*28+1
#define NK      197           // 14*14+1
#define SCALE   0.10206207261596577f   // 96^-0.5

typedef unsigned long long u64;
typedef unsigned int u32;

__device__ __forceinline__ u64 pk2(float a, float b) {
    u64 r; asm("mov.b64 %0,{%1,%2};" : "=l"(r) : "f"(a), "f"(b)); return r;
}
__device__ __forceinline__ void upk2(u64 v, float& a, float& b) {
    asm("mov.b64 {%0,%1},%2;" : "=f"(a), "=f"(b) : "l"(v));
}
__device__ __forceinline__ u64 ffma2(u64 a, u64 b, u64 c) {
    u64 d; asm("fma.rn.f32x2 %0,%1,%2,%3;" : "=l"(d) : "l"(a), "l"(b), "l"(c)); return d;
}
// pack two fp32 -> bf16x2 (lo in low half, hi in high half)
__device__ __forceinline__ u32 bf2(float lo, float hi) {
    u32 r; asm("cvt.rn.bf16x2.f32 %0, %1, %2;" : "=r"(r) : "f"(hi), "f"(lo)); return r;
}
// single fp32 -> bf16 in low 16 bits
__device__ __forceinline__ unsigned short bf1(float v) {
    unsigned short r; asm("cvt.rn.bf16.f32 %0, %1;" : "=h"(r) : "f"(v)); return r;
}
__device__ __forceinline__ void mma_bf16(float* d, const u32* a, u32 b0, u32 b1) {
    asm volatile("mma.sync.aligned.m16n8k16.row.col.f32.bf16.bf16.f32 "
        "{%0,%1,%2,%3},{%4,%5,%6,%7},{%8,%9},{%0,%1,%2,%3};"
        : "+f"(d[0]), "+f"(d[1]), "+f"(d[2]), "+f"(d[3])
        : "r"(a[0]), "r"(a[1]), "r"(a[2]), "r"(a[3]), "r"(b0), "r"(b1));
}

// ---------------- scratch (device globals) ----------------
__device__ float g_qln[BATCH * NQ * CIN];
__device__ float g_kln[BATCH * NK * CIN];
__device__ float g_vln[BATCH * NK * CIN];
__device__ float g_qp [BATCH * NQ * COUT];
__device__ float g_kp [BATCH * NK * COUT];
__device__ float g_vp [BATCH * NK * COUT];
__device__ float g_ehw[BATCH * NHEAD * 784 * 28];   // per (b,h,spatial q): eh[14] | ew[14]

// =====================================================================
// Kernel 1: depthwise 3x3 pool (stride s, pad 1) + LayerNorm over C=96
// =====================================================================
__global__ void pool_ln_kernel(const float* __restrict__ hs,
                               const float* __restrict__ pw,
                               const float* __restrict__ gam,
                               const float* __restrict__ bet,
                               float* __restrict__ out,
                               int stride, int Wout, int ntok)
{
    int warp = threadIdx.x >> 5;
    int lane = threadIdx.x & 31;
    int tok  = blockIdx.x * (blockDim.x >> 5) + warp;
    if (tok >= BATCH * ntok) return;
    int b = tok / ntok;
    int t = tok - b * ntok;

    float v0 = 0.f, v1 = 0.f, v2 = 0.f;
    if (t == 0) {
        const float* p = hs + (size_t)b * NTOT * CIN;
        v0 = p[lane]; v1 = p[lane + 32]; v2 = p[lane + 64];
    } else {
        int s   = t - 1;
        int y   = s / Wout, x = s - y * Wout;
        int iy0 = y * stride - 1, ix0 = x * stride - 1;
        #pragma unroll
        for (int dy = 0; dy < 3; dy++) {
            int iy = iy0 + dy;
            if (iy < 0 || iy >= HFS) continue;
            #pragma unroll
            for (int dx = 0; dx < 3; dx++) {
                int ix = ix0 + dx;
                if (ix < 0 || ix >= HFS) continue;
                const float* p = hs + ((size_t)b * NTOT + 1 + iy * HFS + ix) * CIN;
                int w = dy * 3 + dx;
                v0 += pw[(lane)      * 9 + w] * p[lane];
                v1 += pw[(lane + 32) * 9 + w] * p[lane + 32];
                v2 += pw[(lane + 64) * 9 + w] * p[lane + 64];
            }
        }
    }
    float su  = v0 + v1 + v2;
    float sq  = v0 * v0 + v1 * v1 + v2 * v2;
    #pragma unroll
    for (int o = 16; o; o >>= 1) {
        su += __shfl_xor_sync(0xffffffffu, su, o);
        sq += __shfl_xor_sync(0xffffffffu, sq, o);
    }
    float mean = su * (1.f / 96.f);
    float var  = sq * (1.f / 96.f) - mean * mean;
    float rs   = rsqrtf(var + 1e-5f);
    float* o = out + (size_t)tok * CIN;
    o[lane]      = (v0 - mean) * rs * gam[lane]      + bet[lane];
    o[lane + 32] = (v1 - mean) * rs * gam[lane + 32] + bet[lane + 32];
    o[lane + 64] = (v2 - mean) * rs * gam[lane + 64] + bet[lane + 64];
}

// =====================================================================
// Kernel 2: projection GEMM  Y[M,192] = X[M,96] @ W[96,192] + bias
// (fp32 FFMA2 — q feeds the residual so precision must stay fp32)
// =====================================================================
#define PROJ_SMEM ((96 * 192 + 96 * 66) * 4)
__global__ __launch_bounds__(256, 2)
void proj_kernel(const float* __restrict__ X,
                 const float* __restrict__ W,
                 const float* __restrict__ bias,
                 float* __restrict__ Y, int M)
{
    extern __shared__ float sh[];
    float* sW  = sh;
    float* sXt = sh + 96 * 192;
    int tid  = threadIdx.x;
    int lane = tid & 31;
    int rg   = tid >> 5;
    int row0 = blockIdx.x * 64;

    for (int i = tid; i < 96 * 192; i += 256) sW[i] = W[i];
    for (int i = tid; i < 64 * 96; i += 256) {
        int r = i / 96, k = i - r * 96;
        int gr = row0 + r;
        sXt[k * 66 + r] = (gr < M) ? X[(size_t)gr * 96 + k] : 0.f;
    }
    __syncthreads();

    u64 acc[4][6];
    #pragma unroll
    for (int i = 0; i < 6; i++) {
        float bv = bias[lane + 32 * i];
        u64 b2 = pk2(bv, bv);
        #pragma unroll
        for (int rp = 0; rp < 4; rp++) acc[rp][i] = b2;
    }

    const float* xw = sXt + rg * 8;
    #pragma unroll 4
    for (int k = 0; k < 96; k++) {
        u64 x01 = *(const u64*)(xw + k * 66);
        u64 x23 = *(const u64*)(xw + k * 66 + 2);
        u64 x45 = *(const u64*)(xw + k * 66 + 4);
        u64 x67 = *(const u64*)(xw + k * 66 + 6);
        #pragma unroll
        for (int i = 0; i < 6; i++) {
            float wv = sW[k * 192 + lane + 32 * i];
            u64 w2 = pk2(wv, wv);
            acc[0][i] = ffma2(x01, w2, acc[0][i]);
            acc[1][i] = ffma2(x23, w2, acc[1][i]);
            acc[2][i] = ffma2(x45, w2, acc[2][i]);
            acc[3][i] = ffma2(x67, w2, acc[3][i]);
        }
    }

    #pragma unroll
    for (int rp = 0; rp < 4; rp++) {
        int gr0 = row0 + rg * 8 + 2 * rp;
        #pragma unroll
        for (int i = 0; i < 6; i++) {
            float a, bv;
            upk2(acc[rp][i], a, bv);
            int n = lane + 32 * i;
            if (gr0 < M)     Y[(size_t)gr0 * 192 + n]       = a;
            if (gr0 + 1 < M) Y[(size_t)(gr0 + 1) * 192 + n] = bv;
        }
    }
}

// =====================================================================
// Kernel 2b: rel-pos bias table.
// =====================================================================
#define REL_SMEM ((2 * 55 * 98 + 64 * 96) * 4)
__global__ __launch_bounds__(256, 1)
void rel_kernel(const float* __restrict__ relh,
                const float* __restrict__ relw)
{
    extern __shared__ float sh[];
    float* sR = sh;                 // [2][55][98]
    float* sQ = sh + 2 * 55 * 98;   // [64][96]
    int tid = threadIdx.x;
    int row0 = blockIdx.x * 64;
    const int TOTAL = BATCH * NHEAD * 784;

    for (int i = tid; i < 2 * 55 * 96; i += 256) {
        int tab = i / (55 * 96);
        int rem = i - tab * (55 * 96);
        int r = rem / 96, c = rem - r * 96;
        sR[(tab * 55 + r) * 98 + c] = tab ? relw[r * 96 + c] : relh[r * 96 + c];
    }
    for (int i = tid; i < 64 * 96; i += 256) {
        int lr = i / 96, c = i - lr * 96;
        int rid = row0 + lr;
        float v = 0.f;
        if (rid < TOTAL) {
            int bh = rid / 784, s = rid - bh * 784;
            int b = bh >> 1, h = bh & 1;
            v = g_qp[((size_t)b * NQ + s + 1) * COUT + h * HDIM + c];
        }
        sQ[lr * 96 + c] = v;
    }
    __syncthreads();

    int warp = tid >> 5, lane = tid & 31;
    bool isH = (lane < 14);
    bool isW = (lane >= 16 && lane < 30);
    int  kk  = isH ? lane : (lane - 16);

    #pragma unroll
    for (int rr = 0; rr < 8; rr++) {
        int lr = warp * 8 + rr;
        int rid = row0 + lr;
        if (rid >= TOTAL) continue;
        int s = rid % 784;
        int qy = s / QH, qx = s - qy * QH;
        int coord = isH ? qy : qx;
        int idx = coord - 2 * kk + 26;
        int tab = isH ? 0 : 1;
        if (!(isH || isW)) idx = 0;
        const float* R = sR + (tab * 55 + idx) * 98;
        const float* q = sQ + lr * 96;
        u64 a2 = 0;
        #pragma unroll 8
        for (int c2 = 0; c2 < 48; c2++)
            a2 = ffma2(*(const u64*)(q + 2 * c2), *(const u64*)(R + 2 * c2), a2);
        float a, b2v;
        upk2(a2, a, b2v);
        if (isH || isW)
            g_ehw[(size_t)rid * 28 + tab * 14 + kk] = a + b2v;
    }
}

// =====================================================================
// Kernel 3: fused attention, bf16 mma.sync, P kept in registers
// (C-fragment of S == A-fragment of P after bf16x2 packing).
// smem (bytes):
//   sK   [200][104] bf16  @ 0      (pre-scaled K, rows>=197 zero)   41600
//   sVt  [96][216]  bf16  @ 41600  (V transposed, cols>=197 zero)   41472
//   sEHW 12w x [16][28] fp32 @ 83072                                21504
// total 104576
// =====================================================================
#define SK_OFF   0
#define SVT_OFF  41600
#define SEHW_OFF 83072
#define ATTN_SMEM 104576

__global__ __launch_bounds__(384, 1)
void attn_kernel(float* __restrict__ out)
{
    extern __shared__ char smem[];
    char* sK  = smem + SK_OFF;
    char* sVt = smem + SVT_OFF;
    int b    = blockIdx.x >> 1;
    int head = blockIdx.x & 1;
    int tid  = threadIdx.x;
    int warp = tid >> 5, lane = tid & 31;
    int g = lane >> 2, t = lane & 3;

    float* sEHW = (float*)(smem + SEHW_OFF) + warp * 448;  // [16][28]

    // ---- stage K (scaled, bf16) ----
    for (int i = tid; i < 200 * 96; i += 384) {
        int j = i / 96, c = i - j * 96;
        float v = 0.f;
        if (j < NK) v = SCALE * g_kp[((size_t)b * NK + j) * COUT + head * HDIM + c];
        *(unsigned short*)(sK + (j * 104 + c) * 2) = bf1(v);
    }
    // ---- stage V transposed (bf16) ----
    for (int i = tid; i < 96 * 216; i += 384) {
        int c = i / 216, j = i - c * 216;
        float v = 0.f;
        if (j < NK) v = g_vp[((size_t)b * NK + j) * COUT + head * HDIM + c];
        *(unsigned short*)(sVt + (c * 216 + j) * 2) = bf1(v);
    }
    __syncthreads();

    const float* qbase = g_qp + (size_t)b * NQ * COUT + head * HDIM;
    int bh = b * 2 + head;

    for (int tile = warp; tile < 50; tile += 12) {
        int q0 = tile * 16;
        int r0 = q0 + g, r1 = q0 + g + 8;
        int r0c = (r0 < NQ) ? r0 : NQ - 1;
        int r1c = (r1 < NQ) ? r1 : NQ - 1;

        // ---- stage rel bias rows for this tile ----
        for (int idx = lane; idx < 448; idx += 32) {
            int r = idx / 28, k = idx - r * 28;
            int gr = q0 + r;
            float v = 0.f;
            if (gr >= 1 && gr < NQ)
                v = g_ehw[((size_t)bh * 784 + gr - 1) * 28 + k];
            sEHW[idx] = v;
        }

        // ---- load Q A-fragments (bf16) ----
        const float* q_r0 = qbase + (size_t)r0c * COUT;
        const float* q_r1 = qbase + (size_t)r1c * COUT;
        u32 a[6][4];
        #pragma unroll
        for (int ks = 0; ks < 6; ks++) {
            float2 x0 = *(const float2*)(q_r0 + 16 * ks + 2 * t);
            float2 x1 = *(const float2*)(q_r1 + 16 * ks + 2 * t);
            float2 x2 = *(const float2*)(q_r0 + 16 * ks + 2 * t + 8);
            float2 x3 = *(const float2*)(q_r1 + 16 * ks + 2 * t + 8);
            a[ks][0] = bf2(x0.x, x0.y);
            a[ks][1] = bf2(x1.x, x1.y);
            a[ks][2] = bf2(x2.x, x2.y);
            a[ks][3] = bf2(x3.x, x3.y);
        }
        __syncwarp();

        // ---- QK^T: 25 n-tiles x 6 k-steps ----
        float acc[25][4];
        #pragma unroll
        for (int nt = 0; nt < 25; nt++)
            #pragma unroll
            for (int i = 0; i < 4; i++) acc[nt][i] = 0.f;

        #pragma unroll
        for (int nt = 0; nt < 25; nt++) {
            const char* kb = sK + ((8 * nt + g) * 104 + 2 * t) * 2;
            #pragma unroll
            for (int ks = 0; ks < 6; ks++) {
                u32 b0 = *(const u32*)(kb + 16 * ks * 2);
                u32 b1 = *(const u32*)(kb + (16 * ks + 8) * 2);
                mma_bf16(acc[nt], a[ks], b0, b1);
            }
        }

        // ---- bias + exp + sum (no max subtraction; logits bounded) ----
        const float* elo = sEHW + g * 28;
        const float* ehi = sEHW + (g + 8) * 28;
        float slo = 0.f, shi = 0.f;
        #pragma unroll
        for (int nt = 0; nt < 25; nt++) {
            #pragma unroll
            for (int jo = 0; jo < 2; jo++) {
                int j = 8 * nt + 2 * t + jo;
                float e0, e1;
                if (j >= NK) {
                    e0 = 0.f; e1 = 0.f;
                } else if (j == 0) {
                    e0 = __expf(acc[nt][jo]);
                    e1 = __expf(acc[nt][2 + jo]);
                } else {
                    int ky = (j - 1) / 14;
                    int kx = (j - 1) - ky * 14;
                    e0 = __expf(acc[nt][jo]     + elo[ky] + elo[14 + kx]);
                    e1 = __expf(acc[nt][2 + jo] + ehi[ky] + ehi[14 + kx]);
                }
                acc[nt][jo]     = e0; slo += e0;
                acc[nt][2 + jo] = e1; shi += e1;
            }
        }
        slo += __shfl_xor_sync(0xffffffffu, slo, 1);
        slo += __shfl_xor_sync(0xffffffffu, slo, 2);
        shi += __shfl_xor_sync(0xffffffffu, shi, 1);
        shi += __shfl_xor_sync(0xffffffffu, shi, 2);
        float ilo = 1.f / slo, ihi = 1.f / shi;

        // ---- pack P directly into A-fragments (C layout == A layout) ----
        u32 pP[26][2];
        #pragma unroll
        for (int nt = 0; nt < 25; nt++) {
            pP[nt][0] = bf2(acc[nt][0] * ilo, acc[nt][1] * ilo);
            pP[nt][1] = bf2(acc[nt][2] * ihi, acc[nt][3] * ihi);
        }
        pP[25][0] = 0u; pP[25][1] = 0u;

        // ---- AV: 13 k-steps x 12 n-tiles ----
        float o[12][4];
        #pragma unroll
        for (int nt = 0; nt < 12; nt++)
            #pragma unroll
            for (int i = 0; i < 4; i++) o[nt][i] = 0.f;

        #pragma unroll
        for (int ks = 0; ks < 13; ks++) {
            u32 pa[4];
            pa[0] = pP[2 * ks][0];
            pa[1] = pP[2 * ks][1];
            pa[2] = pP[2 * ks + 1][0];
            pa[3] = pP[2 * ks + 1][1];
            #pragma unroll
            for (int nt = 0; nt < 12; nt++) {
                const char* vb = sVt + ((8 * nt + g) * 216 + 16 * ks + 2 * t) * 2;
                u32 b0 = *(const u32*)(vb);
                u32 b1 = *(const u32*)(vb + 16);
                mma_bf16(o[nt], pa, b0, b1);
            }
        }

        // ---- residual + store ----
        float* obase = out + (size_t)b * NQ * COUT + head * HDIM;
        #pragma unroll
        for (int nt = 0; nt < 12; nt++) {
            int c = 8 * nt + 2 * t;
            if (r0 < NQ) {
                float2 r = make_float2(o[nt][0], o[nt][1]);
                if (r0 >= 1) {
                    float2 q = *(const float2*)(qbase + (size_t)r0 * COUT + c);
                    r.x += q.x; r.y += q.y;
                }
                *(float2*)(obase + (size_t)r0 * COUT + c) = r;
            }
            if (r1 < NQ) {
                float2 r = make_float2(o[nt][2], o[nt][3]);
                if (r1 >= 1) {
                    float2 q = *(const float2*)(qbase + (size_t)r1 * COUT + c);
                    r.x += q.x; r.y += q.y;
                }
                *(float2*)(obase + (size_t)r1 * COUT + c) = r;
            }
        }
        __syncwarp();
    }
}

// =====================================================================
// launch
// =====================================================================
extern "C" void kernel_launch(void* const* d_in, const int* in_sizes, int n_in,
                              void* d_out, int out_size)
{
    const float* hs    = (const float*)d_in[0];
    const float* Wq    = (const float*)d_in[1];
    const float* bq    = (const float*)d_in[2];
    const float* Wk    = (const float*)d_in[3];
    const float* bk    = (const float*)d_in[4];
    const float* Wv    = (const float*)d_in[5];
    const float* bv    = (const float*)d_in[6];
    const float* pqw   = (const float*)d_in[7];
    const float* pkw   = (const float*)d_in[8];
    const float* pvw   = (const float*)d_in[9];
    const float* gq    = (const float*)d_in[10];
    const float* betaq = (const float*)d_in[11];
    const float* gk    = (const float*)d_in[12];
    const float* betak = (const float*)d_in[13];
    const float* gv    = (const float*)d_in[14];
    const float* betav = (const float*)d_in[15];
    const float* relh  = (const float*)d_in[16];
    const float* relw  = (const float*)d_in[17];
    float* out = (float*)d_out;

    float *qln, *kln, *vln, *qp, *kp, *vp;
    cudaGetSymbolAddress((void**)&qln, g_qln);
    cudaGetSymbolAddress((void**)&kln, g_kln);
    cudaGetSymbolAddress((void**)&vln, g_vln);
    cudaGetSymbolAddress((void**)&qp,  g_qp);
    cudaGetSymbolAddress((void**)&kp,  g_kp);
    cudaGetSymbolAddress((void**)&vp,  g_vp);

    cudaFuncSetAttribute(proj_kernel, cudaFuncAttributeMaxDynamicSharedMemorySize, PROJ_SMEM);
    cudaFuncSetAttribute(rel_kernel,  cudaFuncAttributeMaxDynamicSharedMemorySize, REL_SMEM);
    cudaFuncSetAttribute(attn_kernel, cudaFuncAttributeMaxDynamicSharedMemorySize, ATTN_SMEM);

    // pooling + LN
    pool_ln_kernel<<<(BATCH * NQ + 7) / 8, 256>>>(hs, pqw, gq, betaq, qln, 2, QH, NQ);
    pool_ln_kernel<<<(BATCH * NK + 7) / 8, 256>>>(hs, pkw, gk, betak, kln, 4, KH, NK);
    pool_ln_kernel<<<(BATCH * NK + 7) / 8, 256>>>(hs, pvw, gv, betav, vln, 4, KH, NK);

    // projections (fp32)
    int Mq = BATCH * NQ;
    int Mk = BATCH * NK;
    proj_kernel<<<(Mq + 63) / 64, 256, PROJ_SMEM>>>(qln, Wq, bq, qp, Mq);
    proj_kernel<<<(Mk + 63) / 64, 256, PROJ_SMEM>>>(kln, Wk, bk, kp, Mk);
    proj_kernel<<<(Mk + 63) / 64, 256, PROJ_SMEM>>>(vln, Wv, bv, vp, Mk);

    // rel-pos bias table (needs q projection)
    rel_kernel<<<(BATCH * NHEAD * 784 + 63) / 64, 256, REL_SMEM>>>(relh, relw);

    // fused tensor-core attention
    attn_kernel<<<BATCH * NHEAD, 384, ATTN_SMEM>>>(out);
}